// round 15
// baseline (speedup 1.0000x reference)
#include <cuda_runtime.h>
#include <cuda_fp16.h>
#include <math.h>
#include <stdint.h>

#define B_DIM 4096
#define U_DIM 1024
#define N_TOT 6144
#define K_EXT 2048            // single-pass fp16

#define NCHUNK 128
#define CHUNK (B_DIM / NCHUNK)   // 32

// ============================ scratch =====================================
__device__ __half g_act[(size_t)B_DIM * 4 * U_DIM];     // activated f,i,o,c_hat (fp16)
__device__ float  g_z[(size_t)B_DIM * 2 * U_DIM];       // raw zft | zit (fp32)
__device__ __half g_soft[(size_t)B_DIM * 2 * U_DIM];    // fp16 softmax outputs
__device__ float  g_part[NCHUNK * 2 * U_DIM];           // chunk sums -> exclusive prefix
__device__ __half g_Aext[(size_t)B_DIM * K_EXT];        // [4096, 2048] row-major
__device__ __half g_Bext[(size_t)N_TOT * K_EXT];        // [6144, 2048] N-major (K contiguous)

struct WPtrs    { const float* W[6]; const float* U[6]; };
struct BiasPtrs { const float* b[6]; };

__device__ __forceinline__ uint32_t smem_to_u32(const void* p) {
    uint32_t a;
    asm("{ .reg .u64 t; cvta.to.shared.u64 t, %1; cvt.u32.u64 %0, t; }" : "=r"(a) : "l"(p));
    return a;
}
__device__ __forceinline__ uint32_t sw128(uint32_t off) {
    return off ^ ((off >> 3) & 0x70);
}
// fast exact-formula activations: MUFU-based, ~1e-6 relative error
__device__ __forceinline__ float sigmoidf_(float x) {
    return __fdividef(1.f, 1.f + __expf(-x));
}
__device__ __forceinline__ float tanhf_(float x) {
    return 1.f - __fdividef(2.f, __expf(2.f * x) + 1.f);
}

// ==================== fused conversion kernel (A + B) =====================
// blocks [0, 8192): A conversion; blocks [8192, 20480): B transpose+convert
#define BUILD_A_BLOCKS (B_DIM * K_EXT / 4 / 256)     // 8192
#define BUILD_B_BLOCKS (64 * 32 * 6)                 // 12288

__global__ __launch_bounds__(256) void build_AB_kernel(const float* __restrict__ inp,
                                                       const float* __restrict__ hid,
                                                       WPtrs wp) {
    if (blockIdx.x < BUILD_A_BLOCKS) {
        int idx = (blockIdx.x * 256 + threadIdx.x) * 4;   // over B_DIM*K_EXT elements
        int m = idx >> 11;
        int k = idx & 2047;
        const float* src = (k < 1024) ? (inp + (size_t)m * 1024 + k)
                                      : (hid + (size_t)m * 1024 + (k - 1024));
        float4 v = *(const float4*)src;
        __half2* dst = (__half2*)(g_Aext + (size_t)m * K_EXT + k);
        dst[0] = __floats2half2_rn(v.x, v.y);
        dst[1] = __floats2half2_rn(v.z, v.w);
        return;
    }
    __shared__ float tile[32][33];
    int rem = blockIdx.x - BUILD_A_BLOCKS;
    int g   = rem / 2048;
    int r2  = rem % 2048;
    int k0  = (r2 & 63) * 32;    // k within [0,2048)
    int c0  = (r2 >> 6) * 32;    // col within gate
    const float* src = (k0 < 1024) ? wp.W[g] : wp.U[g];
    int ks = (k0 < 1024) ? k0 : (k0 - 1024);
    int tx = threadIdx.x & 31, ty4 = threadIdx.x >> 5;
#pragma unroll
    for (int i = 0; i < 4; i++) {
        int ty = ty4 * 4 + i;
        tile[ty][tx] = src[(size_t)(ks + ty) * 1024 + c0 + tx];
    }
    __syncthreads();
    int kp = threadIdx.x & 15;       // k pair index (2 k each)
    int r0 = threadIdx.x >> 4;       // 0..15
#pragma unroll
    for (int h = 0; h < 2; h++) {
        int r = r0 + h * 16;
        float x0 = tile[2 * kp][r];
        float x1 = tile[2 * kp + 1][r];
        *(__half2*)(g_Bext + (size_t)((g << 10) + c0 + r) * K_EXT + k0 + 2 * kp) =
            __floats2half2_rn(x0, x1);
    }
}

// ======================= mma.sync fp16 GEMM (R10 config) ===================
#define BM 128
#define BN 128
#define BK 64
#define STAGES 3
#define NCHUNKS (K_EXT / BK)          // 32
#define A_BYTES (BM * 128)            // 16KB
#define B_BYTES (BN * 128)            // 16KB
#define STAGE_BYTES (A_BYTES + B_BYTES)               // 32KB
#define SMEM_GEMM_TOTAL (STAGES * STAGE_BYTES)        // 96KB

__device__ __forceinline__ void cp16(uint32_t saddr, const void* gaddr) {
    asm volatile("cp.async.cg.shared.global [%0], [%1], 16;\n" :: "r"(saddr), "l"(gaddr));
}

__device__ __forceinline__ void load_tiles(uint32_t sA, uint32_t sB,
                                           const __half* Ag,
                                           const __half* Bg, int tid) {
#pragma unroll
    for (int t = 0; t < 8; t++) {                 // A: 128 rows x 128B
        int idx = tid + t * 128;
        int r = idx >> 3, c = idx & 7;
        uint32_t off = (uint32_t)(r * 128 + c * 16);
        cp16(sA + sw128(off), (const char*)Ag + (size_t)r * (K_EXT * 2) + c * 16);
    }
#pragma unroll
    for (int t = 0; t < 8; t++) {                 // B: 128 rows x 128B
        int idx = tid + t * 128;
        int r = idx >> 3, c = idx & 7;
        uint32_t off = (uint32_t)(r * 128 + c * 16);
        cp16(sB + sw128(off), (const char*)Bg + (size_t)r * (K_EXT * 2) + c * 16);
    }
    asm volatile("cp.async.commit_group;\n" ::: "memory");
}

#define LDSM_X4(dst, addr) \
    asm volatile("ldmatrix.sync.aligned.m8n8.x4.shared.b16 {%0,%1,%2,%3}, [%4];" \
                 : "=r"((dst)[0]), "=r"((dst)[1]), "=r"((dst)[2]), "=r"((dst)[3]) : "r"(addr))

__global__ void __launch_bounds__(128, 2) mma_gemm_kernel(BiasPtrs bp) {
    extern __shared__ __align__(1024) char smem[];
    const uint32_t smem_base = smem_to_u32(smem);
    const int tid  = threadIdx.x;
    const int lane = tid & 31;
    const int wid  = tid >> 5;         // 0..3
    const int wm   = wid & 1;          // M half (64 rows)
    const int wn   = wid >> 1;         // N half (64 cols)
    const int m0   = blockIdx.y * BM;
    const int bn0  = blockIdx.x * BN;

    const __half* Ag = g_Aext + (size_t)m0 * K_EXT;
    const __half* Bg = g_Bext + (size_t)bn0 * K_EXT;

    float acc[4][8][4];
#pragma unroll
    for (int i = 0; i < 4; i++)
#pragma unroll
        for (int j = 0; j < 8; j++)
#pragma unroll
            for (int q = 0; q < 4; q++) acc[i][j][q] = 0.f;

    // prologue: stages 0,1
    load_tiles(smem_base + 0 * STAGE_BYTES, smem_base + 0 * STAGE_BYTES + A_BYTES,
               Ag, Bg, tid);
    load_tiles(smem_base + 1 * STAGE_BYTES, smem_base + 1 * STAGE_BYTES + A_BYTES,
               Ag + BK, Bg + BK, tid);

    const uint32_t a_row  = (lane & 7) + ((lane >> 3) & 1) * 8;   // 0..15
    const uint32_t a_byte = (lane >> 4) * 16;                     // k-half
    const uint32_t b_row  = (lane & 7) + (lane >> 4) * 8;         // 0..15
    const uint32_t b_byte = ((lane >> 3) & 1) * 16;               // k-half

    uint32_t af[2][4][4], bf[2][4][4];

#pragma unroll 1
    for (int i = 0; i < NCHUNKS; i++) {
        if (i == NCHUNKS - 1)
            asm volatile("cp.async.wait_group 0;\n" ::: "memory");
        else
            asm volatile("cp.async.wait_group 1;\n" ::: "memory");
        __syncthreads();

        const int s = i % STAGES;
        const uint32_t sA = smem_base + s * STAGE_BYTES;
        const uint32_t sB = sA + A_BYTES;

#pragma unroll
        for (int buf = 0; buf < 2; buf++) {
            const uint32_t koff = (uint32_t)buf * 32;
#pragma unroll
            for (int mi = 0; mi < 4; mi++) {
                uint32_t row = wm * 64 + mi * 16 + a_row;
                LDSM_X4(af[buf][mi], sA + sw128(row * 128 + a_byte + koff));
            }
#pragma unroll
            for (int np = 0; np < 4; np++) {
                uint32_t row = wn * 64 + np * 16 + b_row;
                LDSM_X4(bf[buf][np], sB + sw128(row * 128 + b_byte + koff));
            }
        }

#pragma unroll
        for (int kk = 0; kk < 4; kk++) {
            const int cur = kk & 1;
#pragma unroll
            for (int mi = 0; mi < 4; mi++)
#pragma unroll
                for (int ni = 0; ni < 8; ni++) {
                    uint32_t b0 = bf[cur][ni >> 1][(ni & 1) * 2 + 0];
                    uint32_t b1 = bf[cur][ni >> 1][(ni & 1) * 2 + 1];
                    asm volatile(
                        "mma.sync.aligned.m16n8k16.row.col.f32.f16.f16.f32 "
                        "{%0,%1,%2,%3}, {%4,%5,%6,%7}, {%8,%9}, {%0,%1,%2,%3};"
                        : "+f"(acc[mi][ni][0]), "+f"(acc[mi][ni][1]),
                          "+f"(acc[mi][ni][2]), "+f"(acc[mi][ni][3])
                        : "r"(af[cur][mi][0]), "r"(af[cur][mi][1]),
                          "r"(af[cur][mi][2]), "r"(af[cur][mi][3]),
                          "r"(b0), "r"(b1));
                }

            if (kk == 0 && i + 2 < NCHUNKS) {
                const int s2 = (i + 2) % STAGES;
                load_tiles(smem_base + s2 * STAGE_BYTES,
                           smem_base + s2 * STAGE_BYTES + A_BYTES,
                           Ag + (size_t)(i + 2) * BK, Bg + (size_t)(i + 2) * BK, tid);
            }

            if (kk < 2) {
                const uint32_t koff = (uint32_t)(kk + 2) * 32;
#pragma unroll
                for (int mi = 0; mi < 4; mi++) {
                    uint32_t row = wm * 64 + mi * 16 + a_row;
                    LDSM_X4(af[cur][mi], sA + sw128(row * 128 + a_byte + koff));
                }
#pragma unroll
                for (int np = 0; np < 4; np++) {
                    uint32_t row = wn * 64 + np * 16 + b_row;
                    LDSM_X4(bf[cur][np], sB + sw128(row * 128 + b_byte + koff));
                }
            }
        }
    }

    // ===== fused epilogue: bias + activation, compact stores =====
    const int gate = bn0 >> 10;              // uniform per CTA
    const float* bias = bp.b[gate];
    const int ncg0 = (bn0 & 1023) + wn * 64;
#pragma unroll
    for (int mi = 0; mi < 4; mi++) {
        int m = m0 + wm * 64 + mi * 16 + (lane >> 2);
#pragma unroll
        for (int ni = 0; ni < 8; ni++) {
            int ncg = ncg0 + ni * 8 + 2 * (lane & 3);
            float bx = bias[ncg], by = bias[ncg + 1];
            float z0x = acc[mi][ni][0] + bx, z0y = acc[mi][ni][1] + by;
            float z1x = acc[mi][ni][2] + bx, z1y = acc[mi][ni][3] + by;
            if (gate < 4) {
                float a0x, a0y, a1x, a1y;
                if (gate == 3) {
                    a0x = tanhf_(z0x); a0y = tanhf_(z0y);
                    a1x = tanhf_(z1x); a1y = tanhf_(z1y);
                } else {
                    a0x = sigmoidf_(z0x); a0y = sigmoidf_(z0y);
                    a1x = sigmoidf_(z1x); a1y = sigmoidf_(z1y);
                }
                __half* p0 = g_act + (size_t)m * (4 * U_DIM) + (gate << 10) + ncg;
                __half* p1 = p0 + (size_t)8 * (4 * U_DIM);
                *(__half2*)p0 = __floats2half2_rn(a0x, a0y);
                *(__half2*)p1 = __floats2half2_rn(a1x, a1y);
            } else {
                float* p0 = g_z + (size_t)m * (2 * U_DIM) + ((gate - 4) << 10) + ncg;
                float* p1 = p0 + (size_t)8 * (2 * U_DIM);
                *(float2*)p0 = make_float2(z0x, z0y);
                *(float2*)p1 = make_float2(z1x, z1y);
            }
        }
    }
}

// ========================= softmax / cumsum / final =======================
// warp-per-(row,gate): no barriers, no smem. grid 2048 x 256 (8 warps/block).
__global__ __launch_bounds__(256) void softmax_kernel() {
    const int widx = blockIdx.x * 8 + (threadIdx.x >> 5);   // 0..8191
    const int b    = widx >> 1;
    const int gate = widx & 1;
    const int lane = threadIdx.x & 31;
    const float4* row4 = (const float4*)(g_z + (size_t)b * (2 * U_DIM) + (size_t)gate * U_DIM);
    __half* out = g_soft + (size_t)b * (2 * U_DIM) + (size_t)gate * U_DIM;

    float4 v[8];
#pragma unroll
    for (int i = 0; i < 8; i++) v[i] = row4[i * 32 + lane];

    float m = -1e30f;
#pragma unroll
    for (int i = 0; i < 8; i++)
        m = fmaxf(m, fmaxf(fmaxf(v[i].x, v[i].y), fmaxf(v[i].z, v[i].w)));
#pragma unroll
    for (int o = 16; o; o >>= 1) m = fmaxf(m, __shfl_xor_sync(0xffffffffu, m, o));

    float s = 0.f;
#pragma unroll
    for (int i = 0; i < 8; i++) {
        v[i].x = __expf(v[i].x - m); v[i].y = __expf(v[i].y - m);
        v[i].z = __expf(v[i].z - m); v[i].w = __expf(v[i].w - m);
        s += (v[i].x + v[i].y) + (v[i].z + v[i].w);
    }
#pragma unroll
    for (int o = 16; o; o >>= 1) s += __shfl_xor_sync(0xffffffffu, s, o);
    float inv = 1.f / s;

#pragma unroll
    for (int i = 0; i < 8; i++) {
        __half2 o0 = __floats2half2_rn(v[i].x * inv, v[i].y * inv);
        __half2 o1 = __floats2half2_rn(v[i].z * inv, v[i].w * inv);
        *(__half2*)(out + (i * 32 + lane) * 4)     = o0;
        *(__half2*)(out + (i * 32 + lane) * 4 + 2) = o1;
    }
}

// grid (4, NCHUNK), 256 threads; each thread sums 2 consecutive cols over CHUNK rows
__global__ __launch_bounds__(256) void partial_kernel() {
    const int u = (blockIdx.x * 256 + threadIdx.x) * 2;  // 0..4094 step 2
    const int c = blockIdx.y;
    float sx = 0.f, sy = 0.f;
    const __half* base = g_soft + (size_t)(c * CHUNK) * (2 * U_DIM) + u;
#pragma unroll 4
    for (int r = 0; r < CHUNK; r++) {
        float2 t = __half22float2(*(const __half2*)(base + (size_t)r * (2 * U_DIM)));
        sx += t.x; sy += t.y;
    }
    *(float2*)(g_part + c * (2 * U_DIM) + u) = make_float2(sx, sy);
}

__global__ __launch_bounds__(256) void scan_kernel() {
    const int u = blockIdx.x * 256 + threadIdx.x;
    float v[NCHUNK];
#pragma unroll
    for (int c = 0; c < NCHUNK; c++) v[c] = g_part[c * (2 * U_DIM) + u];
    float run = 0.f;
#pragma unroll
    for (int c = 0; c < NCHUNK; c++) { float t = v[c]; v[c] = run; run += t; }
#pragma unroll
    for (int c = 0; c < NCHUNK; c++) g_part[c * (2 * U_DIM) + u] = v[c];
}

// 128 threads, each handles 2 consecutive u: grid (4, NCHUNK)
__global__ __launch_bounds__(128) void final_kernel(const float* __restrict__ cell_prev,
                                                    float* __restrict__ out) {
    const int u = (blockIdx.x * 128 + threadIdx.x) * 2;  // 0..1022 step 2
    const int c = blockIdx.y;
    float2 runF = *(const float2*)(g_part + c * (2 * U_DIM) + u);
    float2 runI = *(const float2*)(g_part + c * (2 * U_DIM) + U_DIM + u);
#pragma unroll 4
    for (int r = 0; r < CHUNK; r++) {
        const int b = c * CHUNK + r;
        const __half* act = g_act + (size_t)b * (4 * U_DIM);
        float2 f  = __half22float2(*(const __half2*)(act + u));
        float2 ii = __half22float2(*(const __half2*)(act + U_DIM + u));
        float2 oo = __half22float2(*(const __half2*)(act + 2 * U_DIM + u));
        float2 ch = __half22float2(*(const __half2*)(act + 3 * U_DIM + u));
        float2 sf = __half22float2(*(const __half2*)(g_soft + (size_t)b * (2 * U_DIM) + u));
        float2 si = __half22float2(*(const __half2*)(g_soft + (size_t)b * (2 * U_DIM) + U_DIM + u));
        float2 cp = *(const float2*)(cell_prev + (size_t)b * U_DIM + u);
        runF.x += sf.x; runF.y += sf.y;
        runI.x += si.x; runI.y += si.y;

        float2 hid, cell;
        {
            float ft = runF.x, it = 1.f - runI.x;
            float omega = ft * it;
            float fh = f.x * omega + (ft - omega);
            float ih = ii.x * omega + (it - omega);
            cell.x = fh * cp.x + ih * ch.x;
            hid.x = oo.x * tanhf_(cell.x);
        }
        {
            float ft = runF.y, it = 1.f - runI.y;
            float omega = ft * it;
            float fh = f.y * omega + (ft - omega);
            float ih = ii.y * omega + (it - omega);
            cell.y = fh * cp.y + ih * ch.y;
            hid.y = oo.y * tanhf_(cell.y);
        }
        *(float2*)(out + (size_t)b * U_DIM + u) = hid;
        *(float2*)(out + (size_t)B_DIM * U_DIM + (size_t)b * U_DIM + u) = cell;
    }
}

// ============================== launch ====================================
extern "C" void kernel_launch(void* const* d_in, const int* in_sizes, int n_in,
                              void* d_out, int out_size) {
    (void)in_sizes; (void)n_in; (void)out_size;
    const float* inputs      = (const float*)d_in[0];
    const float* hidden_prev = (const float*)d_in[1];
    const float* cell_prev   = (const float*)d_in[2];

    WPtrs wp; BiasPtrs bp;
    for (int g = 0; g < 6; g++) {
        wp.W[g] = (const float*)d_in[3 + 3 * g + 0];
        wp.U[g] = (const float*)d_in[3 + 3 * g + 1];
        bp.b[g] = (const float*)d_in[3 + 3 * g + 2];
    }

    build_AB_kernel<<<BUILD_A_BLOCKS + BUILD_B_BLOCKS, 256>>>(inputs, hidden_prev, wp); // 1

    cudaFuncSetAttribute(mma_gemm_kernel, cudaFuncAttributeMaxDynamicSharedMemorySize,
                         SMEM_GEMM_TOTAL);
    mma_gemm_kernel<<<dim3(N_TOT / BN, B_DIM / BM), 128, SMEM_GEMM_TOTAL>>>(bp);        // 2

    softmax_kernel<<<B_DIM * 2 / 8, 256>>>();                                           // 3
    partial_kernel<<<dim3(4, NCHUNK), 256>>>();                                         // 4 (profiled)
    scan_kernel<<<2 * U_DIM / 256, 256>>>();                                            // 5
    final_kernel<<<dim3(4, NCHUNK), 128>>>(cell_prev, (float*)d_out);                   // 6
}

// round 16
// speedup vs baseline: 1.0133x; 1.0133x over previous
#include <cuda_runtime.h>
#include <cuda_fp16.h>
#include <math.h>
#include <stdint.h>

#define B_DIM 4096
#define U_DIM 1024
#define N_TOT 6144
#define K_EXT 2048            // single-pass fp16

#define NCHUNK 128
#define CHUNK (B_DIM / NCHUNK)   // 32

// ============================ scratch =====================================
__device__ __half g_act[(size_t)B_DIM * 4 * U_DIM];     // activated f,i,o,c_hat (fp16)
__device__ float  g_z[(size_t)B_DIM * 2 * U_DIM];       // raw zft | zit (fp32)
__device__ __half g_soft[(size_t)B_DIM * 2 * U_DIM];    // fp16 softmax outputs
__device__ float  g_part[NCHUNK * 2 * U_DIM];           // chunk sums -> exclusive prefix
__device__ __half g_Aext[(size_t)B_DIM * K_EXT];        // [4096, 2048] row-major
__device__ __half g_Bext[(size_t)N_TOT * K_EXT];        // [6144, 2048] N-major (K contiguous)

struct WPtrs    { const float* W[6]; const float* U[6]; };
struct BiasPtrs { const float* b[6]; };

__device__ __forceinline__ uint32_t smem_to_u32(const void* p) {
    uint32_t a;
    asm("{ .reg .u64 t; cvta.to.shared.u64 t, %1; cvt.u32.u64 %0, t; }" : "=r"(a) : "l"(p));
    return a;
}
__device__ __forceinline__ uint32_t sw128(uint32_t off) {
    return off ^ ((off >> 3) & 0x70);
}
__device__ __forceinline__ float sigmoidf_(float x) { return 1.f / (1.f + __expf(-x)); }

// ========================= conversion kernels =============================
__global__ __launch_bounds__(256) void build_A_kernel(const float* __restrict__ inp,
                                                      const float* __restrict__ hid) {
    int idx = (blockIdx.x * 256 + threadIdx.x) * 4;   // over B_DIM*K_EXT elements
    int m = idx >> 11;
    int k = idx & 2047;
    const float* src = (k < 1024) ? (inp + (size_t)m * 1024 + k)
                                  : (hid + (size_t)m * 1024 + (k - 1024));
    float4 v = *(const float4*)src;
    __half2* dst = (__half2*)(g_Aext + (size_t)m * K_EXT + k);
    dst[0] = __floats2half2_rn(v.x, v.y);
    dst[1] = __floats2half2_rn(v.z, v.w);
}

__global__ __launch_bounds__(256) void build_B_kernel(WPtrs wp) {
    __shared__ float tile[32][33];
    int g  = blockIdx.z;
    int k0 = blockIdx.x * 32;   // k within [0,2048)
    int c0 = blockIdx.y * 32;   // col within gate
    const float* src = (k0 < 1024) ? wp.W[g] : wp.U[g];
    int ks = (k0 < 1024) ? k0 : (k0 - 1024);
    int tx = threadIdx.x & 31, ty4 = threadIdx.x >> 5;
#pragma unroll
    for (int i = 0; i < 4; i++) {
        int ty = ty4 * 4 + i;
        tile[ty][tx] = src[(size_t)(ks + ty) * 1024 + c0 + tx];
    }
    __syncthreads();
    int kp = threadIdx.x & 15;       // k pair index (2 k each)
    int r0 = threadIdx.x >> 4;       // 0..15
#pragma unroll
    for (int h = 0; h < 2; h++) {
        int r = r0 + h * 16;
        float x0 = tile[2 * kp][r];
        float x1 = tile[2 * kp + 1][r];
        *(__half2*)(g_Bext + (size_t)((g << 10) + c0 + r) * K_EXT + k0 + 2 * kp) =
            __floats2half2_rn(x0, x1);
    }
}

// ======================= mma.sync fp16 GEMM (R10 config) ===================
#define BM 128
#define BN 128
#define BK 64
#define STAGES 3
#define NCHUNKS (K_EXT / BK)          // 32
#define A_BYTES (BM * 128)            // 16KB
#define B_BYTES (BN * 128)            // 16KB
#define STAGE_BYTES (A_BYTES + B_BYTES)               // 32KB
#define SMEM_GEMM_TOTAL (STAGES * STAGE_BYTES)        // 96KB

__device__ __forceinline__ void cp16(uint32_t saddr, const void* gaddr) {
    asm volatile("cp.async.cg.shared.global [%0], [%1], 16;\n" :: "r"(saddr), "l"(gaddr));
}

__device__ __forceinline__ void load_tiles(uint32_t sA, uint32_t sB,
                                           const __half* Ag,
                                           const __half* Bg, int tid) {
#pragma unroll
    for (int t = 0; t < 8; t++) {                 // A: 128 rows x 128B
        int idx = tid + t * 128;
        int r = idx >> 3, c = idx & 7;
        uint32_t off = (uint32_t)(r * 128 + c * 16);
        cp16(sA + sw128(off), (const char*)Ag + (size_t)r * (K_EXT * 2) + c * 16);
    }
#pragma unroll
    for (int t = 0; t < 8; t++) {                 // B: 128 rows x 128B
        int idx = tid + t * 128;
        int r = idx >> 3, c = idx & 7;
        uint32_t off = (uint32_t)(r * 128 + c * 16);
        cp16(sB + sw128(off), (const char*)Bg + (size_t)r * (K_EXT * 2) + c * 16);
    }
    asm volatile("cp.async.commit_group;\n" ::: "memory");
}

#define LDSM_X4(dst, addr) \
    asm volatile("ldmatrix.sync.aligned.m8n8.x4.shared.b16 {%0,%1,%2,%3}, [%4];" \
                 : "=r"((dst)[0]), "=r"((dst)[1]), "=r"((dst)[2]), "=r"((dst)[3]) : "r"(addr))

__global__ void __launch_bounds__(128, 2) mma_gemm_kernel(BiasPtrs bp) {
    extern __shared__ __align__(1024) char smem[];
    const uint32_t smem_base = smem_to_u32(smem);
    const int tid  = threadIdx.x;
    const int lane = tid & 31;
    const int wid  = tid >> 5;         // 0..3
    const int wm   = wid & 1;          // M half (64 rows)
    const int wn   = wid >> 1;         // N half (64 cols)
    const int m0   = blockIdx.y * BM;
    const int bn0  = blockIdx.x * BN;

    const __half* Ag = g_Aext + (size_t)m0 * K_EXT;
    const __half* Bg = g_Bext + (size_t)bn0 * K_EXT;

    float acc[4][8][4];
#pragma unroll
    for (int i = 0; i < 4; i++)
#pragma unroll
        for (int j = 0; j < 8; j++)
#pragma unroll
            for (int q = 0; q < 4; q++) acc[i][j][q] = 0.f;

    // prologue: stages 0,1
    load_tiles(smem_base + 0 * STAGE_BYTES, smem_base + 0 * STAGE_BYTES + A_BYTES,
               Ag, Bg, tid);
    load_tiles(smem_base + 1 * STAGE_BYTES, smem_base + 1 * STAGE_BYTES + A_BYTES,
               Ag + BK, Bg + BK, tid);

    const uint32_t a_row  = (lane & 7) + ((lane >> 3) & 1) * 8;   // 0..15
    const uint32_t a_byte = (lane >> 4) * 16;                     // k-half
    const uint32_t b_row  = (lane & 7) + (lane >> 4) * 8;         // 0..15
    const uint32_t b_byte = ((lane >> 3) & 1) * 16;               // k-half

    uint32_t af[2][4][4], bf[2][4][4];

#pragma unroll 1
    for (int i = 0; i < NCHUNKS; i++) {
        if (i == NCHUNKS - 1)
            asm volatile("cp.async.wait_group 0;\n" ::: "memory");
        else
            asm volatile("cp.async.wait_group 1;\n" ::: "memory");
        __syncthreads();

        const int s = i % STAGES;
        const uint32_t sA = smem_base + s * STAGE_BYTES;
        const uint32_t sB = sA + A_BYTES;

#pragma unroll
        for (int buf = 0; buf < 2; buf++) {
            const uint32_t koff = (uint32_t)buf * 32;
#pragma unroll
            for (int mi = 0; mi < 4; mi++) {
                uint32_t row = wm * 64 + mi * 16 + a_row;
                LDSM_X4(af[buf][mi], sA + sw128(row * 128 + a_byte + koff));
            }
#pragma unroll
            for (int np = 0; np < 4; np++) {
                uint32_t row = wn * 64 + np * 16 + b_row;
                LDSM_X4(bf[buf][np], sB + sw128(row * 128 + b_byte + koff));
            }
        }

#pragma unroll
        for (int kk = 0; kk < 4; kk++) {
            const int cur = kk & 1;
#pragma unroll
            for (int mi = 0; mi < 4; mi++)
#pragma unroll
                for (int ni = 0; ni < 8; ni++) {
                    uint32_t b0 = bf[cur][ni >> 1][(ni & 1) * 2 + 0];
                    uint32_t b1 = bf[cur][ni >> 1][(ni & 1) * 2 + 1];
                    asm volatile(
                        "mma.sync.aligned.m16n8k16.row.col.f32.f16.f16.f32 "
                        "{%0,%1,%2,%3}, {%4,%5,%6,%7}, {%8,%9}, {%0,%1,%2,%3};"
                        : "+f"(acc[mi][ni][0]), "+f"(acc[mi][ni][1]),
                          "+f"(acc[mi][ni][2]), "+f"(acc[mi][ni][3])
                        : "r"(af[cur][mi][0]), "r"(af[cur][mi][1]),
                          "r"(af[cur][mi][2]), "r"(af[cur][mi][3]),
                          "r"(b0), "r"(b1));
                }

            if (kk == 0 && i + 2 < NCHUNKS) {
                const int s2 = (i + 2) % STAGES;
                load_tiles(smem_base + s2 * STAGE_BYTES,
                           smem_base + s2 * STAGE_BYTES + A_BYTES,
                           Ag + (size_t)(i + 2) * BK, Bg + (size_t)(i + 2) * BK, tid);
            }

            if (kk < 2) {
                const uint32_t koff = (uint32_t)(kk + 2) * 32;
#pragma unroll
                for (int mi = 0; mi < 4; mi++) {
                    uint32_t row = wm * 64 + mi * 16 + a_row;
                    LDSM_X4(af[cur][mi], sA + sw128(row * 128 + a_byte + koff));
                }
#pragma unroll
                for (int np = 0; np < 4; np++) {
                    uint32_t row = wn * 64 + np * 16 + b_row;
                    LDSM_X4(bf[cur][np], sB + sw128(row * 128 + b_byte + koff));
                }
            }
        }
    }

    // ===== fused epilogue: bias + activation, compact stores =====
    const int gate = bn0 >> 10;              // uniform per CTA
    const float* bias = bp.b[gate];
    const int ncg0 = (bn0 & 1023) + wn * 64;
#pragma unroll
    for (int mi = 0; mi < 4; mi++) {
        int m = m0 + wm * 64 + mi * 16 + (lane >> 2);
#pragma unroll
        for (int ni = 0; ni < 8; ni++) {
            int ncg = ncg0 + ni * 8 + 2 * (lane & 3);
            float bx = bias[ncg], by = bias[ncg + 1];
            float z0x = acc[mi][ni][0] + bx, z0y = acc[mi][ni][1] + by;
            float z1x = acc[mi][ni][2] + bx, z1y = acc[mi][ni][3] + by;
            if (gate < 4) {
                float a0x, a0y, a1x, a1y;
                if (gate == 3) {
                    a0x = tanhf(z0x); a0y = tanhf(z0y);
                    a1x = tanhf(z1x); a1y = tanhf(z1y);
                } else {
                    a0x = sigmoidf_(z0x); a0y = sigmoidf_(z0y);
                    a1x = sigmoidf_(z1x); a1y = sigmoidf_(z1y);
                }
                __half* p0 = g_act + (size_t)m * (4 * U_DIM) + (gate << 10) + ncg;
                __half* p1 = p0 + (size_t)8 * (4 * U_DIM);
                *(__half2*)p0 = __floats2half2_rn(a0x, a0y);
                *(__half2*)p1 = __floats2half2_rn(a1x, a1y);
            } else {
                float* p0 = g_z + (size_t)m * (2 * U_DIM) + ((gate - 4) << 10) + ncg;
                float* p1 = p0 + (size_t)8 * (2 * U_DIM);
                *(float2*)p0 = make_float2(z0x, z0y);
                *(float2*)p1 = make_float2(z1x, z1y);
            }
        }
    }
}

// ========================= softmax / cumsum / final =======================
// warp-per-(row,gate): no barriers, no smem. grid 2048 x 256 (8 warps/block).
__global__ __launch_bounds__(256) void softmax_kernel() {
    const int widx = blockIdx.x * 8 + (threadIdx.x >> 5);   // 0..8191
    const int b    = widx >> 1;
    const int gate = widx & 1;
    const int lane = threadIdx.x & 31;
    const float4* row4 = (const float4*)(g_z + (size_t)b * (2 * U_DIM) + (size_t)gate * U_DIM);
    __half* out = g_soft + (size_t)b * (2 * U_DIM) + (size_t)gate * U_DIM;

    float4 v[8];
#pragma unroll
    for (int i = 0; i < 8; i++) v[i] = row4[i * 32 + lane];

    float m = -1e30f;
#pragma unroll
    for (int i = 0; i < 8; i++)
        m = fmaxf(m, fmaxf(fmaxf(v[i].x, v[i].y), fmaxf(v[i].z, v[i].w)));
#pragma unroll
    for (int o = 16; o; o >>= 1) m = fmaxf(m, __shfl_xor_sync(0xffffffffu, m, o));

    float s = 0.f;
#pragma unroll
    for (int i = 0; i < 8; i++) {
        v[i].x = __expf(v[i].x - m); v[i].y = __expf(v[i].y - m);
        v[i].z = __expf(v[i].z - m); v[i].w = __expf(v[i].w - m);
        s += (v[i].x + v[i].y) + (v[i].z + v[i].w);
    }
#pragma unroll
    for (int o = 16; o; o >>= 1) s += __shfl_xor_sync(0xffffffffu, s, o);
    float inv = 1.f / s;

#pragma unroll
    for (int i = 0; i < 8; i++) {
        __half2 o0 = __floats2half2_rn(v[i].x * inv, v[i].y * inv);
        __half2 o1 = __floats2half2_rn(v[i].z * inv, v[i].w * inv);
        *(__half2*)(out + (i * 32 + lane) * 4)     = o0;
        *(__half2*)(out + (i * 32 + lane) * 4 + 2) = o1;
    }
}

// grid (4, NCHUNK), 256 threads; each thread sums 2 consecutive cols over CHUNK rows.
// FULLY unrolled: 32 independent strided loads front-batched for MLP (latency fix).
__global__ __launch_bounds__(256) void partial_kernel() {
    const int u = (blockIdx.x * 256 + threadIdx.x) * 2;  // 0..4094 step 2
    const int c = blockIdx.y;
    float sx = 0.f, sy = 0.f;
    const __half* base = g_soft + (size_t)(c * CHUNK) * (2 * U_DIM) + u;
#pragma unroll
    for (int r = 0; r < CHUNK; r++) {
        float2 t = __half22float2(*(const __half2*)(base + (size_t)r * (2 * U_DIM)));
        sx += t.x; sy += t.y;
    }
    *(float2*)(g_part + c * (2 * U_DIM) + u) = make_float2(sx, sy);
}

__global__ __launch_bounds__(256) void scan_kernel() {
    const int u = blockIdx.x * 256 + threadIdx.x;
    float v[NCHUNK];
#pragma unroll
    for (int c = 0; c < NCHUNK; c++) v[c] = g_part[c * (2 * U_DIM) + u];
    float run = 0.f;
#pragma unroll
    for (int c = 0; c < NCHUNK; c++) { float t = v[c]; v[c] = run; run += t; }
#pragma unroll
    for (int c = 0; c < NCHUNK; c++) g_part[c * (2 * U_DIM) + u] = v[c];
}

// 128 threads, each handles 2 consecutive u: grid (4, NCHUNK)
__global__ __launch_bounds__(128) void final_kernel(const float* __restrict__ cell_prev,
                                                    float* __restrict__ out) {
    const int u = (blockIdx.x * 128 + threadIdx.x) * 2;  // 0..1022 step 2
    const int c = blockIdx.y;
    float2 runF = *(const float2*)(g_part + c * (2 * U_DIM) + u);
    float2 runI = *(const float2*)(g_part + c * (2 * U_DIM) + U_DIM + u);
#pragma unroll 4
    for (int r = 0; r < CHUNK; r++) {
        const int b = c * CHUNK + r;
        const __half* act = g_act + (size_t)b * (4 * U_DIM);
        float2 f  = __half22float2(*(const __half2*)(act + u));
        float2 ii = __half22float2(*(const __half2*)(act + U_DIM + u));
        float2 oo = __half22float2(*(const __half2*)(act + 2 * U_DIM + u));
        float2 ch = __half22float2(*(const __half2*)(act + 3 * U_DIM + u));
        float2 sf = __half22float2(*(const __half2*)(g_soft + (size_t)b * (2 * U_DIM) + u));
        float2 si = __half22float2(*(const __half2*)(g_soft + (size_t)b * (2 * U_DIM) + U_DIM + u));
        float2 cp = *(const float2*)(cell_prev + (size_t)b * U_DIM + u);
        runF.x += sf.x; runF.y += sf.y;
        runI.x += si.x; runI.y += si.y;

        float2 hid, cell;
        {
            float ft = runF.x, it = 1.f - runI.x;
            float omega = ft * it;
            float fh = f.x * omega + (ft - omega);
            float ih = ii.x * omega + (it - omega);
            cell.x = fh * cp.x + ih * ch.x;
            hid.x = oo.x * tanhf(cell.x);
        }
        {
            float ft = runF.y, it = 1.f - runI.y;
            float omega = ft * it;
            float fh = f.y * omega + (ft - omega);
            float ih = ii.y * omega + (it - omega);
            cell.y = fh * cp.y + ih * ch.y;
            hid.y = oo.y * tanhf(cell.y);
        }
        *(float2*)(out + (size_t)b * U_DIM + u) = hid;
        *(float2*)(out + (size_t)B_DIM * U_DIM + (size_t)b * U_DIM + u) = cell;
    }
}

// ============================== launch ====================================
extern "C" void kernel_launch(void* const* d_in, const int* in_sizes, int n_in,
                              void* d_out, int out_size) {
    (void)in_sizes; (void)n_in; (void)out_size;
    const float* inputs      = (const float*)d_in[0];
    const float* hidden_prev = (const float*)d_in[1];
    const float* cell_prev   = (const float*)d_in[2];

    WPtrs wp; BiasPtrs bp;
    for (int g = 0; g < 6; g++) {
        wp.W[g] = (const float*)d_in[3 + 3 * g + 0];
        wp.U[g] = (const float*)d_in[3 + 3 * g + 1];
        bp.b[g] = (const float*)d_in[3 + 3 * g + 2];
    }

    build_A_kernel<<<(B_DIM * K_EXT / 4) / 256, 256>>>(inputs, hidden_prev);  // launch 1
    build_B_kernel<<<dim3(64, 32, 6), 256>>>(wp);                             // launch 2

    cudaFuncSetAttribute(mma_gemm_kernel, cudaFuncAttributeMaxDynamicSharedMemorySize,
                         SMEM_GEMM_TOTAL);
    mma_gemm_kernel<<<dim3(N_TOT / BN, B_DIM / BM), 128, SMEM_GEMM_TOTAL>>>(bp);  // launch 3

    softmax_kernel<<<B_DIM * 2 / 8, 256>>>();                                 // launch 4 (profiled)
    partial_kernel<<<dim3(4, NCHUNK), 256>>>();                               // launch 5
    scan_kernel<<<2 * U_DIM / 256, 256>>>();                                  // launch 6
    final_kernel<<<dim3(4, NCHUNK), 128>>>(cell_prev, (float*)d_out);         // launch 7
}

// round 17
// speedup vs baseline: 1.0476x; 1.0339x over previous
#include <cuda_runtime.h>
#include <cuda_fp16.h>
#include <math.h>
#include <stdint.h>

#define B_DIM 4096
#define U_DIM 1024
#define N_TOT 6144
#define K_EXT 2048            // single-pass fp16

#define NCHUNK 128
#define CHUNK (B_DIM / NCHUNK)   // 32

// ============================ scratch =====================================
__device__ __half g_act[(size_t)B_DIM * 4 * U_DIM];     // activated f,i,o,c_hat (fp16)
__device__ float  g_z[(size_t)B_DIM * 2 * U_DIM];       // raw zft | zit (fp32)
__device__ __half g_soft[(size_t)B_DIM * 2 * U_DIM];    // fp16 softmax outputs
__device__ float  g_part[NCHUNK * 2 * U_DIM];           // chunk sums -> exclusive prefix
__device__ __half g_Aext[(size_t)B_DIM * K_EXT];        // [4096, 2048] row-major
__device__ __half g_Bext[(size_t)N_TOT * K_EXT];        // [6144, 2048] N-major (K contiguous)

struct WPtrs    { const float* W[6]; const float* U[6]; };
struct BiasPtrs { const float* b[6]; };

__device__ __forceinline__ uint32_t smem_to_u32(const void* p) {
    uint32_t a;
    asm("{ .reg .u64 t; cvta.to.shared.u64 t, %1; cvt.u32.u64 %0, t; }" : "=r"(a) : "l"(p));
    return a;
}
__device__ __forceinline__ uint32_t sw128(uint32_t off) {
    return off ^ ((off >> 3) & 0x70);
}
// fast activations: MUFU-based exact identities, ~1e-6 relative error
__device__ __forceinline__ float sigmoidf_(float x) {
    return __fdividef(1.f, 1.f + __expf(-x));
}
__device__ __forceinline__ float tanhf_(float x) {
    return 1.f - __fdividef(2.f, __expf(2.f * x) + 1.f);
}

// ========================= conversion kernels =============================
__global__ __launch_bounds__(256) void build_A_kernel(const float* __restrict__ inp,
                                                      const float* __restrict__ hid) {
    int idx = (blockIdx.x * 256 + threadIdx.x) * 4;   // over B_DIM*K_EXT elements
    int m = idx >> 11;
    int k = idx & 2047;
    const float* src = (k < 1024) ? (inp + (size_t)m * 1024 + k)
                                  : (hid + (size_t)m * 1024 + (k - 1024));
    float4 v = *(const float4*)src;
    __half2* dst = (__half2*)(g_Aext + (size_t)m * K_EXT + k);
    dst[0] = __floats2half2_rn(v.x, v.y);
    dst[1] = __floats2half2_rn(v.z, v.w);
}

__global__ __launch_bounds__(256) void build_B_kernel(WPtrs wp) {
    __shared__ float tile[32][33];
    int g  = blockIdx.z;
    int k0 = blockIdx.x * 32;   // k within [0,2048)
    int c0 = blockIdx.y * 32;   // col within gate
    const float* src = (k0 < 1024) ? wp.W[g] : wp.U[g];
    int ks = (k0 < 1024) ? k0 : (k0 - 1024);
    int tx = threadIdx.x & 31, ty4 = threadIdx.x >> 5;
#pragma unroll
    for (int i = 0; i < 4; i++) {
        int ty = ty4 * 4 + i;
        tile[ty][tx] = src[(size_t)(ks + ty) * 1024 + c0 + tx];
    }
    __syncthreads();
    int kp = threadIdx.x & 15;       // k pair index (2 k each)
    int r0 = threadIdx.x >> 4;       // 0..15
#pragma unroll
    for (int h = 0; h < 2; h++) {
        int r = r0 + h * 16;
        float x0 = tile[2 * kp][r];
        float x1 = tile[2 * kp + 1][r];
        *(__half2*)(g_Bext + (size_t)((g << 10) + c0 + r) * K_EXT + k0 + 2 * kp) =
            __floats2half2_rn(x0, x1);
    }
}

// ======================= mma.sync fp16 GEMM (R10 config) ===================
#define BM 128
#define BN 128
#define BK 64
#define STAGES 3
#define NCHUNKS (K_EXT / BK)          // 32
#define A_BYTES (BM * 128)            // 16KB
#define B_BYTES (BN * 128)            // 16KB
#define STAGE_BYTES (A_BYTES + B_BYTES)               // 32KB
#define SMEM_GEMM_TOTAL (STAGES * STAGE_BYTES)        // 96KB

__device__ __forceinline__ void cp16(uint32_t saddr, const void* gaddr) {
    asm volatile("cp.async.cg.shared.global [%0], [%1], 16;\n" :: "r"(saddr), "l"(gaddr));
}

__device__ __forceinline__ void load_tiles(uint32_t sA, uint32_t sB,
                                           const __half* Ag,
                                           const __half* Bg, int tid) {
#pragma unroll
    for (int t = 0; t < 8; t++) {                 // A: 128 rows x 128B
        int idx = tid + t * 128;
        int r = idx >> 3, c = idx & 7;
        uint32_t off = (uint32_t)(r * 128 + c * 16);
        cp16(sA + sw128(off), (const char*)Ag + (size_t)r * (K_EXT * 2) + c * 16);
    }
#pragma unroll
    for (int t = 0; t < 8; t++) {                 // B: 128 rows x 128B
        int idx = tid + t * 128;
        int r = idx >> 3, c = idx & 7;
        uint32_t off = (uint32_t)(r * 128 + c * 16);
        cp16(sB + sw128(off), (const char*)Bg + (size_t)r * (K_EXT * 2) + c * 16);
    }
    asm volatile("cp.async.commit_group;\n" ::: "memory");
}

#define LDSM_X4(dst, addr) \
    asm volatile("ldmatrix.sync.aligned.m8n8.x4.shared.b16 {%0,%1,%2,%3}, [%4];" \
                 : "=r"((dst)[0]), "=r"((dst)[1]), "=r"((dst)[2]), "=r"((dst)[3]) : "r"(addr))

__global__ void __launch_bounds__(128, 2) mma_gemm_kernel(BiasPtrs bp) {
    extern __shared__ __align__(1024) char smem[];
    const uint32_t smem_base = smem_to_u32(smem);
    const int tid  = threadIdx.x;
    const int lane = tid & 31;
    const int wid  = tid >> 5;         // 0..3
    const int wm   = wid & 1;          // M half (64 rows)
    const int wn   = wid >> 1;         // N half (64 cols)
    const int m0   = blockIdx.y * BM;
    const int bn0  = blockIdx.x * BN;

    const __half* Ag = g_Aext + (size_t)m0 * K_EXT;
    const __half* Bg = g_Bext + (size_t)bn0 * K_EXT;

    float acc[4][8][4];
#pragma unroll
    for (int i = 0; i < 4; i++)
#pragma unroll
        for (int j = 0; j < 8; j++)
#pragma unroll
            for (int q = 0; q < 4; q++) acc[i][j][q] = 0.f;

    // prologue: stages 0,1
    load_tiles(smem_base + 0 * STAGE_BYTES, smem_base + 0 * STAGE_BYTES + A_BYTES,
               Ag, Bg, tid);
    load_tiles(smem_base + 1 * STAGE_BYTES, smem_base + 1 * STAGE_BYTES + A_BYTES,
               Ag + BK, Bg + BK, tid);

    const uint32_t a_row  = (lane & 7) + ((lane >> 3) & 1) * 8;   // 0..15
    const uint32_t a_byte = (lane >> 4) * 16;                     // k-half
    const uint32_t b_row  = (lane & 7) + (lane >> 4) * 8;         // 0..15
    const uint32_t b_byte = ((lane >> 3) & 1) * 16;               // k-half

    uint32_t af[2][4][4], bf[2][4][4];

#pragma unroll 1
    for (int i = 0; i < NCHUNKS; i++) {
        if (i == NCHUNKS - 1)
            asm volatile("cp.async.wait_group 0;\n" ::: "memory");
        else
            asm volatile("cp.async.wait_group 1;\n" ::: "memory");
        __syncthreads();

        const int s = i % STAGES;
        const uint32_t sA = smem_base + s * STAGE_BYTES;
        const uint32_t sB = sA + A_BYTES;

#pragma unroll
        for (int buf = 0; buf < 2; buf++) {
            const uint32_t koff = (uint32_t)buf * 32;
#pragma unroll
            for (int mi = 0; mi < 4; mi++) {
                uint32_t row = wm * 64 + mi * 16 + a_row;
                LDSM_X4(af[buf][mi], sA + sw128(row * 128 + a_byte + koff));
            }
#pragma unroll
            for (int np = 0; np < 4; np++) {
                uint32_t row = wn * 64 + np * 16 + b_row;
                LDSM_X4(bf[buf][np], sB + sw128(row * 128 + b_byte + koff));
            }
        }

#pragma unroll
        for (int kk = 0; kk < 4; kk++) {
            const int cur = kk & 1;
#pragma unroll
            for (int mi = 0; mi < 4; mi++)
#pragma unroll
                for (int ni = 0; ni < 8; ni++) {
                    uint32_t b0 = bf[cur][ni >> 1][(ni & 1) * 2 + 0];
                    uint32_t b1 = bf[cur][ni >> 1][(ni & 1) * 2 + 1];
                    asm volatile(
                        "mma.sync.aligned.m16n8k16.row.col.f32.f16.f16.f32 "
                        "{%0,%1,%2,%3}, {%4,%5,%6,%7}, {%8,%9}, {%0,%1,%2,%3};"
                        : "+f"(acc[mi][ni][0]), "+f"(acc[mi][ni][1]),
                          "+f"(acc[mi][ni][2]), "+f"(acc[mi][ni][3])
                        : "r"(af[cur][mi][0]), "r"(af[cur][mi][1]),
                          "r"(af[cur][mi][2]), "r"(af[cur][mi][3]),
                          "r"(b0), "r"(b1));
                }

            if (kk == 0 && i + 2 < NCHUNKS) {
                const int s2 = (i + 2) % STAGES;
                load_tiles(smem_base + s2 * STAGE_BYTES,
                           smem_base + s2 * STAGE_BYTES + A_BYTES,
                           Ag + (size_t)(i + 2) * BK, Bg + (size_t)(i + 2) * BK, tid);
            }

            if (kk < 2) {
                const uint32_t koff = (uint32_t)(kk + 2) * 32;
#pragma unroll
                for (int mi = 0; mi < 4; mi++) {
                    uint32_t row = wm * 64 + mi * 16 + a_row;
                    LDSM_X4(af[cur][mi], sA + sw128(row * 128 + a_byte + koff));
                }
#pragma unroll
                for (int np = 0; np < 4; np++) {
                    uint32_t row = wn * 64 + np * 16 + b_row;
                    LDSM_X4(bf[cur][np], sB + sw128(row * 128 + b_byte + koff));
                }
            }
        }
    }

    // ===== fused epilogue: bias + activation (fast MUFU), compact stores =====
    const int gate = bn0 >> 10;              // uniform per CTA
    const float* bias = bp.b[gate];
    const int ncg0 = (bn0 & 1023) + wn * 64;
#pragma unroll
    for (int mi = 0; mi < 4; mi++) {
        int m = m0 + wm * 64 + mi * 16 + (lane >> 2);
#pragma unroll
        for (int ni = 0; ni < 8; ni++) {
            int ncg = ncg0 + ni * 8 + 2 * (lane & 3);
            float bx = bias[ncg], by = bias[ncg + 1];
            float z0x = acc[mi][ni][0] + bx, z0y = acc[mi][ni][1] + by;
            float z1x = acc[mi][ni][2] + bx, z1y = acc[mi][ni][3] + by;
            if (gate < 4) {
                float a0x, a0y, a1x, a1y;
                if (gate == 3) {
                    a0x = tanhf_(z0x); a0y = tanhf_(z0y);
                    a1x = tanhf_(z1x); a1y = tanhf_(z1y);
                } else {
                    a0x = sigmoidf_(z0x); a0y = sigmoidf_(z0y);
                    a1x = sigmoidf_(z1x); a1y = sigmoidf_(z1y);
                }
                __half* p0 = g_act + (size_t)m * (4 * U_DIM) + (gate << 10) + ncg;
                __half* p1 = p0 + (size_t)8 * (4 * U_DIM);
                *(__half2*)p0 = __floats2half2_rn(a0x, a0y);
                *(__half2*)p1 = __floats2half2_rn(a1x, a1y);
            } else {
                float* p0 = g_z + (size_t)m * (2 * U_DIM) + ((gate - 4) << 10) + ncg;
                float* p1 = p0 + (size_t)8 * (2 * U_DIM);
                *(float2*)p0 = make_float2(z0x, z0y);
                *(float2*)p1 = make_float2(z1x, z1y);
            }
        }
    }
}

// ========================= softmax / cumsum / final =======================
// warp-per-(row,gate): no barriers, no smem. grid 2048 x 256 (8 warps/block).
__global__ __launch_bounds__(256) void softmax_kernel() {
    const int widx = blockIdx.x * 8 + (threadIdx.x >> 5);   // 0..8191
    const int b    = widx >> 1;
    const int gate = widx & 1;
    const int lane = threadIdx.x & 31;
    const float4* row4 = (const float4*)(g_z + (size_t)b * (2 * U_DIM) + (size_t)gate * U_DIM);
    __half* out = g_soft + (size_t)b * (2 * U_DIM) + (size_t)gate * U_DIM;

    float4 v[8];
#pragma unroll
    for (int i = 0; i < 8; i++) v[i] = row4[i * 32 + lane];

    float m = -1e30f;
#pragma unroll
    for (int i = 0; i < 8; i++)
        m = fmaxf(m, fmaxf(fmaxf(v[i].x, v[i].y), fmaxf(v[i].z, v[i].w)));
#pragma unroll
    for (int o = 16; o; o >>= 1) m = fmaxf(m, __shfl_xor_sync(0xffffffffu, m, o));

    float s = 0.f;
#pragma unroll
    for (int i = 0; i < 8; i++) {
        v[i].x = __expf(v[i].x - m); v[i].y = __expf(v[i].y - m);
        v[i].z = __expf(v[i].z - m); v[i].w = __expf(v[i].w - m);
        s += (v[i].x + v[i].y) + (v[i].z + v[i].w);
    }
#pragma unroll
    for (int o = 16; o; o >>= 1) s += __shfl_xor_sync(0xffffffffu, s, o);
    float inv = 1.f / s;

#pragma unroll
    for (int i = 0; i < 8; i++) {
        __half2 o0 = __floats2half2_rn(v[i].x * inv, v[i].y * inv);
        __half2 o1 = __floats2half2_rn(v[i].z * inv, v[i].w * inv);
        *(__half2*)(out + (i * 32 + lane) * 4)     = o0;
        *(__half2*)(out + (i * 32 + lane) * 4 + 2) = o1;
    }
}

// grid (4, NCHUNK), 256 threads; fully unrolled independent loads (MLP).
__global__ __launch_bounds__(256) void partial_kernel() {
    const int u = (blockIdx.x * 256 + threadIdx.x) * 2;  // 0..4094 step 2
    const int c = blockIdx.y;
    float sx = 0.f, sy = 0.f;
    const __half* base = g_soft + (size_t)(c * CHUNK) * (2 * U_DIM) + u;
#pragma unroll
    for (int r = 0; r < CHUNK; r++) {
        float2 t = __half22float2(*(const __half2*)(base + (size_t)r * (2 * U_DIM)));
        sx += t.x; sy += t.y;
    }
    *(float2*)(g_part + c * (2 * U_DIM) + u) = make_float2(sx, sy);
}

__global__ __launch_bounds__(256) void scan_kernel() {
    const int u = blockIdx.x * 256 + threadIdx.x;
    float v[NCHUNK];
#pragma unroll
    for (int c = 0; c < NCHUNK; c++) v[c] = g_part[c * (2 * U_DIM) + u];
    float run = 0.f;
#pragma unroll
    for (int c = 0; c < NCHUNK; c++) { float t = v[c]; v[c] = run; run += t; }
#pragma unroll
    for (int c = 0; c < NCHUNK; c++) g_part[c * (2 * U_DIM) + u] = v[c];
}

// 128 threads, each handles 2 consecutive u: grid (4, NCHUNK)
__global__ __launch_bounds__(128) void final_kernel(const float* __restrict__ cell_prev,
                                                    float* __restrict__ out) {
    const int u = (blockIdx.x * 128 + threadIdx.x) * 2;  // 0..1022 step 2
    const int c = blockIdx.y;
    float2 runF = *(const float2*)(g_part + c * (2 * U_DIM) + u);
    float2 runI = *(const float2*)(g_part + c * (2 * U_DIM) + U_DIM + u);
#pragma unroll 8
    for (int r = 0; r < CHUNK; r++) {
        const int b = c * CHUNK + r;
        const __half* act = g_act + (size_t)b * (4 * U_DIM);
        float2 f  = __half22float2(*(const __half2*)(act + u));
        float2 ii = __half22float2(*(const __half2*)(act + U_DIM + u));
        float2 oo = __half22float2(*(const __half2*)(act + 2 * U_DIM + u));
        float2 ch = __half22float2(*(const __half2*)(act + 3 * U_DIM + u));
        float2 sf = __half22float2(*(const __half2*)(g_soft + (size_t)b * (2 * U_DIM) + u));
        float2 si = __half22float2(*(const __half2*)(g_soft + (size_t)b * (2 * U_DIM) + U_DIM + u));
        float2 cp = *(const float2*)(cell_prev + (size_t)b * U_DIM + u);
        runF.x += sf.x; runF.y += sf.y;
        runI.x += si.x; runI.y += si.y;

        float2 hid, cell;
        {
            float ft = runF.x, it = 1.f - runI.x;
            float omega = ft * it;
            float fh = f.x * omega + (ft - omega);
            float ih = ii.x * omega + (it - omega);
            cell.x = fh * cp.x + ih * ch.x;
            hid.x = oo.x * tanhf_(cell.x);
        }
        {
            float ft = runF.y, it = 1.f - runI.y;
            float omega = ft * it;
            float fh = f.y * omega + (ft - omega);
            float ih = ii.y * omega + (it - omega);
            cell.y = fh * cp.y + ih * ch.y;
            hid.y = oo.y * tanhf_(cell.y);
        }
        *(float2*)(out + (size_t)b * U_DIM + u) = hid;
        *(float2*)(out + (size_t)B_DIM * U_DIM + (size_t)b * U_DIM + u) = cell;
    }
}

// ============================== launch ====================================
extern "C" void kernel_launch(void* const* d_in, const int* in_sizes, int n_in,
                              void* d_out, int out_size) {
    (void)in_sizes; (void)n_in; (void)out_size;
    const float* inputs      = (const float*)d_in[0];
    const float* hidden_prev = (const float*)d_in[1];
    const float* cell_prev   = (const float*)d_in[2];

    WPtrs wp; BiasPtrs bp;
    for (int g = 0; g < 6; g++) {
        wp.W[g] = (const float*)d_in[3 + 3 * g + 0];
        wp.U[g] = (const float*)d_in[3 + 3 * g + 1];
        bp.b[g] = (const float*)d_in[3 + 3 * g + 2];
    }

    build_A_kernel<<<(B_DIM * K_EXT / 4) / 256, 256>>>(inputs, hidden_prev);  // launch 1
    build_B_kernel<<<dim3(64, 32, 6), 256>>>(wp);                             // launch 2

    cudaFuncSetAttribute(mma_gemm_kernel, cudaFuncAttributeMaxDynamicSharedMemorySize,
                         SMEM_GEMM_TOTAL);
    mma_gemm_kernel<<<dim3(N_TOT / BN, B_DIM / BM), 128, SMEM_GEMM_TOTAL>>>(bp);  // launch 3

    softmax_kernel<<<B_DIM * 2 / 8, 256>>>();                                 // launch 4 (profiled)
    partial_kernel<<<dim3(4, NCHUNK), 256>>>();                               // launch 5
    scan_kernel<<<2 * U_DIM / 256, 256>>>();                                  // launch 6
    final_kernel<<<dim3(4, NCHUNK), 128>>>(cell_prev, (float*)d_out);         // launch 7
}